// round 10
// baseline (speedup 1.0000x reference)
#include <cuda_runtime.h>

#define NT      512
#define RV4     7                 // float4 per thread in registers
#define SJ      9                 // smem float4 iterations per thread
#define N_COLS  32000
#define N4      8000              // float4 per row
#define R4MAX   (RV4 * NT)        // 3584 float4 held in registers
#define SMEM4   (N4 - R4MAX)      // 4416 float4 held in smem
#define SMEM_BYTES (SMEM4 * 16)   // 70656
#define N_ITER  50

__device__ __forceinline__ float warp_sum(float v) {
    #pragma unroll
    for (int o = 16; o > 0; o >>= 1) v += __shfl_xor_sync(0xffffffffu, v, o);
    return v;
}
__device__ __forceinline__ float warp_max(float v) {
    #pragma unroll
    for (int o = 16; o > 0; o >>= 1) v = fmaxf(v, __shfl_xor_sync(0xffffffffu, v, o));
    return v;
}
__device__ __forceinline__ float warp_min(float v) {
    #pragma unroll
    for (int o = 16; o > 0; o >>= 1) v = fminf(v, __shfl_xor_sync(0xffffffffu, v, o));
    return v;
}

__global__ void __launch_bounds__(NT, 2)
entmax_kernel(const float* __restrict__ x, float* __restrict__ out) {
    extern __shared__ float4 sdat[];          // SMEM4 float4, thread-private slots
    __shared__ float s_mx[16];
    __shared__ float s_mn[16];
    __shared__ float s_s1[16];
    __shared__ float s_s2[16];
    __shared__ float s_bc0, s_bc1, s_bc2, s_bc3;

    const int row = blockIdx.x;
    const int tid = threadIdx.x;
    const int wid = tid >> 5;                 // 0..15
    const int lid = tid & 31;

    const float4* __restrict__ xrow =
        reinterpret_cast<const float4*>(x + (size_t)row * N_COLS);
    float4* __restrict__ orow =
        reinterpret_cast<float4*>(out + (size_t)row * N_COLS);

    float4 v[RV4];                            // raw x, never shifted

    // ---- load pass (streaming loads): reg part + smem part; fused stats ----
    float lmax = __int_as_float(0xff800000);  // -inf
    float lmin = __int_as_float(0x7f800000);  // +inf
    float s1 = 0.0f;                          // sum x
    float s2 = 0.0f;                          // sum x^2
    #pragma unroll
    for (int i = 0; i < RV4; i++) {
        float4 a = __ldcs(&xrow[i * NT + tid]);
        v[i] = a;
        lmax = fmaxf(lmax, fmaxf(fmaxf(a.x, a.y), fmaxf(a.z, a.w)));
        lmin = fminf(lmin, fminf(fminf(a.x, a.y), fminf(a.z, a.w)));
        s1 += a.x + a.y + a.z + a.w;
        s2 = fmaf(a.x, a.x, s2); s2 = fmaf(a.y, a.y, s2);
        s2 = fmaf(a.z, a.z, s2); s2 = fmaf(a.w, a.w, s2);
    }
    #pragma unroll
    for (int j = 0; j < SJ; j++) {
        const int idx = R4MAX + j * NT + tid;
        if (idx < N4) {
            float4 a = __ldcs(&xrow[idx]);
            sdat[idx - R4MAX] = a;
            lmax = fmaxf(lmax, fmaxf(fmaxf(a.x, a.y), fmaxf(a.z, a.w)));
            lmin = fminf(lmin, fminf(fminf(a.x, a.y), fminf(a.z, a.w)));
            s1 += a.x + a.y + a.z + a.w;
            s2 = fmaf(a.x, a.x, s2); s2 = fmaf(a.y, a.y, s2);
            s2 = fmaf(a.z, a.z, s2); s2 = fmaf(a.w, a.w, s2);
        }
    }

    // ---- single fused block reduce: max, min, S1, S2 ----
    lmax = warp_max(lmax);
    lmin = warp_min(lmin);
    s1 = warp_sum(s1);
    s2 = warp_sum(s2);
    if (lid == 0) { s_mx[wid] = lmax; s_mn[wid] = lmin; s_s1[wid] = s1; s_s2[wid] = s2; }
    __syncthreads();
    if (wid == 0) {
        float m = (lid < 16) ? s_mx[lid] : -3.4e38f;
        float n = (lid < 16) ? s_mn[lid] :  3.4e38f;
        float a = (lid < 16) ? s_s1[lid] : 0.0f;
        float b = (lid < 16) ? s_s2[lid] : 0.0f;
        m = warp_max(m);
        n = warp_min(n);
        a = warp_sum(a);
        b = warp_sum(b);
        if (lid == 0) { s_bc0 = m; s_bc1 = n; s_bc2 = a; s_bc3 = b; }
    }
    __syncthreads();
    const float maxv = s_bc0;
    const float minv = s_bc1;
    const float S1   = s_bc2;
    const float S2   = s_bc3;

    // ---- scalar fp32 replica of reference recurrence under constraint>0
    //      invariant (tmax <- tau each iter, tmin fixed). Analytically valid
    //      when tau_1^2 > 1: f(tau) >= clip(0-tau)^2 = tau^2 (max elem has
    //      z = 0), f decreasing, all iterates <= tau_1. ----
    const float m_shift = minv - maxv;
    const float tmin0 = m_shift - 1.0f;
    float tmaxr = 0.0f;
    #pragma unroll
    for (int it = 0; it < N_ITER; it++) tmaxr = 0.5f * (tmin0 + tmaxr);
    const float tau_fast = 0.5f * (tmin0 + tmaxr);
    const bool fast = (m_shift <= -1.02f);

    // folded constant: z - tau = fma(0.5, x, -c), c = 0.5*maxv + tau
    const float c_fast = 0.5f * maxv + tau_fast;

    // ---- analytic normalizer (fast path): clip never active because
    //      z_i - tau_fast >= 1 (see R9 derivation). f(tau) =
    //      0.25*S2 - c*S1 + N*c^2. ----
    float cfin  = c_fast;
    float total = fmaf(0.25f, S2, fmaf(-c_fast, S1, (float)N_COLS * c_fast * c_fast));

    if (!fast) {
        // ---- fallback: reference-semantics bisection (regs + smem).
        //      Never taken for this data; guards pathological inputs. ----
        float tmin = tmin0, tmax = 0.0f;
        for (int it = 0; it < N_ITER; it++) {
            const float t = 0.5f * (tmin + tmax);
            const float ct = 0.5f * maxv + t;
            float ss = 0.0f;
            #pragma unroll
            for (int i = 0; i < RV4; i++) {
                float d;
                d = fmaxf(fmaf(0.5f, v[i].x, -ct), 0.0f); ss = fmaf(d, d, ss);
                d = fmaxf(fmaf(0.5f, v[i].y, -ct), 0.0f); ss = fmaf(d, d, ss);
                d = fmaxf(fmaf(0.5f, v[i].z, -ct), 0.0f); ss = fmaf(d, d, ss);
                d = fmaxf(fmaf(0.5f, v[i].w, -ct), 0.0f); ss = fmaf(d, d, ss);
            }
            #pragma unroll
            for (int j = 0; j < SJ; j++) {
                const int idx = R4MAX + j * NT + tid;
                if (idx < N4) {
                    float4 a = sdat[idx - R4MAX];
                    float d;
                    d = fmaxf(fmaf(0.5f, a.x, -ct), 0.0f); ss = fmaf(d, d, ss);
                    d = fmaxf(fmaf(0.5f, a.y, -ct), 0.0f); ss = fmaf(d, d, ss);
                    d = fmaxf(fmaf(0.5f, a.z, -ct), 0.0f); ss = fmaf(d, d, ss);
                    d = fmaxf(fmaf(0.5f, a.w, -ct), 0.0f); ss = fmaf(d, d, ss);
                }
            }
            ss = warp_sum(ss);
            if (lid == 0) s_s1[wid] = ss;
            __syncthreads();
            if (wid == 0) {
                float u = (lid < 16) ? s_s1[lid] : 0.0f;
                u = warp_sum(u);
                if (lid == 0) s_bc0 = u;
            }
            __syncthreads();
            const float constraint = s_bc0 - 1.0f;
            if (constraint < 0.0f) tmin = t;
            if (constraint > 0.0f) tmax = t;
        }
        const float tau = 0.5f * (tmin + tmax);
        cfin = 0.5f * maxv + tau;
        float ss = 0.0f;
        #pragma unroll
        for (int i = 0; i < RV4; i++) {
            float d;
            d = fmaxf(fmaf(0.5f, v[i].x, -cfin), 0.0f); ss = fmaf(d, d, ss);
            d = fmaxf(fmaf(0.5f, v[i].y, -cfin), 0.0f); ss = fmaf(d, d, ss);
            d = fmaxf(fmaf(0.5f, v[i].z, -cfin), 0.0f); ss = fmaf(d, d, ss);
            d = fmaxf(fmaf(0.5f, v[i].w, -cfin), 0.0f); ss = fmaf(d, d, ss);
        }
        #pragma unroll
        for (int j = 0; j < SJ; j++) {
            const int idx = R4MAX + j * NT + tid;
            if (idx < N4) {
                float4 a = sdat[idx - R4MAX];
                float d;
                d = fmaxf(fmaf(0.5f, a.x, -cfin), 0.0f); ss = fmaf(d, d, ss);
                d = fmaxf(fmaf(0.5f, a.y, -cfin), 0.0f); ss = fmaf(d, d, ss);
                d = fmaxf(fmaf(0.5f, a.z, -cfin), 0.0f); ss = fmaf(d, d, ss);
                d = fmaxf(fmaf(0.5f, a.w, -cfin), 0.0f); ss = fmaf(d, d, ss);
            }
        }
        ss = warp_sum(ss);
        if (lid == 0) s_s1[wid] = ss;
        __syncthreads();
        if (wid == 0) {
            float u = (lid < 16) ? s_s1[lid] : 0.0f;
            u = warp_sum(u);
            if (lid == 0) s_bc0 = u;
        }
        __syncthreads();
        total = s_bc0;
    }

    const float inv = 1.0f / (total + 1e-12f);

    // ---- write y = clip(fma(0.5, x, -c), 0)^2 * inv  (streaming stores) ----
    #pragma unroll
    for (int i = 0; i < RV4; i++) {
        float4 o;
        float d;
        d = fmaxf(fmaf(0.5f, v[i].x, -cfin), 0.0f); o.x = d * d * inv;
        d = fmaxf(fmaf(0.5f, v[i].y, -cfin), 0.0f); o.y = d * d * inv;
        d = fmaxf(fmaf(0.5f, v[i].z, -cfin), 0.0f); o.z = d * d * inv;
        d = fmaxf(fmaf(0.5f, v[i].w, -cfin), 0.0f); o.w = d * d * inv;
        __stcs(&orow[i * NT + tid], o);
    }
    #pragma unroll
    for (int j = 0; j < SJ; j++) {
        const int idx = R4MAX + j * NT + tid;
        if (idx < N4) {
            float4 a = sdat[idx - R4MAX];
            float4 o;
            float d;
            d = fmaxf(fmaf(0.5f, a.x, -cfin), 0.0f); o.x = d * d * inv;
            d = fmaxf(fmaf(0.5f, a.y, -cfin), 0.0f); o.y = d * d * inv;
            d = fmaxf(fmaf(0.5f, a.z, -cfin), 0.0f); o.z = d * d * inv;
            d = fmaxf(fmaf(0.5f, a.w, -cfin), 0.0f); o.w = d * d * inv;
            __stcs(&orow[idx], o);
        }
    }
}

extern "C" void kernel_launch(void* const* d_in, const int* in_sizes, int n_in,
                              void* d_out, int out_size) {
    const float* x = (const float*)d_in[0];
    float* out = (float*)d_out;
    const int rows = in_sizes[0] / N_COLS;   // 4096
    cudaFuncSetAttribute(entmax_kernel,
                         cudaFuncAttributeMaxDynamicSharedMemorySize, SMEM_BYTES);
    entmax_kernel<<<rows, NT, SMEM_BYTES>>>(x, out);
}